// round 13
// baseline (speedup 1.0000x reference)
#include <cuda_runtime.h>
#include <cuda_bf16.h>
#include <cstdint>
#include <cstddef>

typedef long long ll;

#define DIM   512
#define VDIM  512
#define VMAX  100000
#define TMAX  2
#define E_    64
#define N_    128
#define G_    16
#define NTHR  256

// ---------------- device scratch (static; no allocation) ----------------
__device__ float g_acc[G_ * N_ * DIM];     // per-graph accumulators
__device__ float g_u0[G_ * E_ * DIM];      // wide ping
__device__ float g_u1[G_ * E_ * DIM];      // wide pong
__device__ float g_npos[G_ * DIM];         // finalized embedding of node pos
__device__ float g_w2[G_ * DIM];
__device__ float g_c0[G_];
__device__ float g_dinv[G_];
__device__ int   g_par[G_ * N_];
__device__ int   g_isint[G_ * N_];
__device__ int   g_onp[G_ * N_];
__device__ int   g_path[G_ * 8];
__device__ int   g_plen[G_];
__device__ int   g_eroot[G_];
__device__ int   g_dataV[N_];
__device__ int   g_typesV[N_];
__device__ int   g_edgesV[N_];
__device__ int   g_posv;

__device__ __forceinline__ int clampi(int v, int lo, int hi) {
    return v < lo ? lo : (v > hi ? hi : v);
}

// ---------------- k_pre: dtype detection + input canonicalization + topology ----
__global__ void __launch_bounds__(128) k_pre(const void* graphs_raw,
                                             const void* a_raw,
                                             const void* b_raw,
                                             const void* c_raw,
                                             const void* pos_raw,
                                             int have_pos) {
    __shared__ int s_not64;
    __shared__ int s_max[3];
    int t = threadIdx.x;
    if (t == 0) { s_not64 = 0; s_max[0] = s_max[1] = s_max[2] = 0; }
    __syncthreads();

    // dtype detection on graphs buffer: first 2048 32-bit words are safe to read
    // under both int32 (exactly 2048 words) and int64 (4096 words) layouts.
    // int64 little-endian: words come in (value<128, 0) pairs. Genuine int32
    // graphs have many nonzero odd-position parent values -> detector fires.
    {
        const unsigned* gw = (const unsigned*)graphs_raw;
        int bad = 0;
        for (int k = t; k < 1024; k += 128) {
            unsigned lo = gw[2 * k], hi = gw[2 * k + 1];
            if (hi != 0u || lo >= 128u) bad = 1;
        }
        if (bad) atomicOr(&s_not64, 1);
    }
    __syncthreads();
    const int is64 = s_not64 ? 0 : 1;

    // value-range classification of the three 128-element int arrays
    const void* abc[3] = { a_raw, b_raw, c_raw };
    for (int arr = 0; arr < 3; arr++) {
        int mx = 0;
        for (int k = t; k < N_; k += 128) {
            int v = is64 ? (int)((const ll*)abc[arr])[k] : ((const int*)abc[arr])[k];
            if (v > mx) mx = v;
        }
        atomicMax(&s_max[arr], mx);
    }
    __syncthreads();

    int di = 0, ti = 0, ei;
    {
        int mx0 = s_max[0], mx1 = s_max[1], mx2 = s_max[2];
        if (mx1 > ((di == 0) ? mx0 : mx1)) di = 1;
        di = (mx1 > mx0) ? 1 : 0;
        if (mx2 > ((di == 0) ? mx0 : mx1)) di = 2;
        ti = (mx1 < mx0) ? 1 : 0;
        if (mx2 < ((ti == 0) ? mx0 : mx1)) ti = 2;
        if (ti == di) { di = 0; ti = 1; }    // degenerate: positional fallback
        ei = 3 - di - ti;
    }

    for (int k = t; k < N_; k += 128) {
        int dvv = is64 ? (int)((const ll*)abc[di])[k] : ((const int*)abc[di])[k];
        int tvv = is64 ? (int)((const ll*)abc[ti])[k] : ((const int*)abc[ti])[k];
        int evv = is64 ? (int)((const ll*)abc[ei])[k] : ((const int*)abc[ei])[k];
        g_dataV[k]  = clampi(dvv, 0, VMAX - 1);
        g_typesV[k] = clampi(tvv, 0, TMAX - 1);
        g_edgesV[k] = clampi(evv, 0, E_ - 1);
    }
    for (int k = t; k < G_ * N_; k += 128) g_onp[k] = 0;
    for (int k = t; k < G_ * 8; k += 128) g_path[k] = 0;
    if (t == 0) {
        int pv = have_pos ? ((const int*)pos_raw)[0] : 5;  // low word ok for i32/i64-LE
        g_posv = clampi(pv, 0, N_ - 1);
    }
    __syncthreads();

    // topology: one thread per graph
    const int posv = g_posv;
    if (t < G_) {
        int g = t;
        int par[N_], cnt[N_];
        for (int i = 0; i < N_; i++) {
            int p = is64 ? (int)((const ll*)graphs_raw)[(size_t)g * N_ + i]
                         : ((const int*)graphs_raw)[(size_t)g * N_ + i];
            par[i] = clampi(p, 0, N_ - 1);
        }
        // chain multiple roots in ascending order; last becomes final root
        int prev = -1, root = 0;
        for (int i = 0; i < N_; i++) {
            if (par[i] == i) { if (prev >= 0) par[prev] = i; prev = i; root = i; }
        }
        par[root] = -1;
        for (int i = 0; i < N_; i++) cnt[i] = 0;
        for (int c = 0; c < N_; c++) if (par[c] >= 0) cnt[par[c]]++;
        int nint = 0;
        for (int i = 0; i < N_; i++) if (cnt[i] > 0) nint++;
        g_dinv[g] = 1.0f / (float)(nint + 1);
        // ancestor path of pos: parent(pos) ... root
        int L = 0, a = par[posv];
        while (a >= 0 && L < 8) {
            g_path[g * 8 + L] = a;
            g_onp[g * N_ + a] = 1;
            L++;
            a = par[a];
        }
        g_plen[g] = L;
        g_eroot[g] = g_edgesV[root];
        for (int i = 0; i < N_; i++) {
            g_par[g * N_ + i] = par[i];
            g_isint[g * N_ + i] = (cnt[i] > 0) ? 1 : 0;
        }
    }
}

// ---------------- k_base: base embeddings, replicated per graph ----------------
__global__ void __launch_bounds__(NTHR) k_base(const float* __restrict__ dv,
                                               const float* __restrict__ dw,
                                               const float* __restrict__ db) {
    __shared__ float sh[VDIM];
    int node = blockIdx.x;
    if (node >= N_) return;
    int t = threadIdx.x;
    int ty = g_typesV[node];
    int dr = g_dataV[node];
    const float* sel = dv + ((size_t)ty * VMAX + (size_t)dr) * VDIM;
    for (int j = t; j < VDIM; j += NTHR) sh[j] = sel[j];
    __syncthreads();
    const float* W = dw + (size_t)ty * VDIM * DIM;
    int d0 = t, d1 = t + NTHR;
    float a0 = 0.f, a1 = 0.f;
#pragma unroll 4
    for (int j = 0; j < VDIM; j++) {
        float v = sh[j];
        a0 += v * W[j * DIM + d0];
        a1 += v * W[j * DIM + d1];
    }
    a0 += db[ty * DIM + d0];
    a1 += db[ty * DIM + d1];
    for (int g = 0; g < G_; g++) {
        g_acc[((size_t)(g * N_ + node)) * DIM + d0] = a0;
        g_acc[((size_t)(g * N_ + node)) * DIM + d1] = a1;
    }
}

// ---------------- k_w2: fold root edge matrix + score weights ----------------
__global__ void __launch_bounds__(NTHR) k_w2(const float* __restrict__ ew,
                                             const float* __restrict__ ebi,
                                             const float* __restrict__ sw) {
    int wid = blockIdx.x * (NTHR / 32) + (threadIdx.x >> 5);
    int lane = threadIdx.x & 31;
    int NW = gridDim.x * (NTHR / 32);
    for (int task = wid; task < G_ * DIM + G_; task += NW) {
        if (task < G_ * DIM) {
            int g = task / DIM, j = task % DIM;
            const float* Wr = ew + ((size_t)g_eroot[g] * DIM + j) * DIM;
            float s = 0.f;
            for (int d = lane; d < DIM; d += 32) s += Wr[d] * sw[d];
            for (int o = 16; o > 0; o >>= 1) s += __shfl_down_sync(0xffffffffu, s, o);
            if (lane == 0) g_w2[g * DIM + j] = s;
        } else {
            int g = task - G_ * DIM;
            const float* br = ebi + (size_t)g_eroot[g] * DIM;
            float s = 0.f;
            for (int d = lane; d < DIM; d += 32) s += br[d] * sw[d];
            for (int o = 16; o > 0; o >>= 1) s += __shfl_down_sync(0xffffffffu, s, o);
            if (lane == 0) g_c0[g] = s;
        }
    }
}

// ---------------- k_nar: sequential per-graph narrow tree reduction -------------
// One block per graph; descending node index is a valid topological order because
// parent(i) < i. No atomics, no grid sync: all RMW traffic is block-local (one L1).
__global__ void __launch_bounds__(512) k_nar(const float* __restrict__ ew,
                                             const float* __restrict__ ebi) {
    __shared__ float x[DIM];
    __shared__ float red[4][DIM];
    const int g = blockIdx.x;
    const int t = threadIdx.x;
    const int q = t >> 7;        // j-quarter 0..3
    const int dg = t & 127;      // output group (4 consecutive d)
    const float dinv = g_dinv[g];
    const int posv = g_posv;

    for (int i = N_ - 1; i >= 1; i--) {
        int p = g_par[g * N_ + i];
        if (p < 0) continue;                 // root (never contributes narrowly)
        if (g_onp[g * N_ + i]) continue;     // path nodes handled in wide phase
        float* accp = g_acc + ((size_t)(g * N_ + i)) * DIM;
        {
            float xx = accp[t];
            if (g_isint[g * N_ + i]) xx = fmaxf(xx * dinv, 0.0f);
            if (i == posv) g_npos[g * DIM + t] = xx;
            x[t] = xx;
        }
        __syncthreads();
        if (i != posv) {
            int e = g_edgesV[i];
            const float4* W4 = (const float4*)(ew + (size_t)e * DIM * DIM);
            float a0 = 0.f, a1 = 0.f, a2 = 0.f, a3 = 0.f;
            int jb = q * 128;
#pragma unroll 8
            for (int jj = 0; jj < 128; jj++) {
                int j = jb + jj;
                float xv = x[j];
                float4 w = W4[j * (DIM / 4) + dg];
                a0 += xv * w.x; a1 += xv * w.y; a2 += xv * w.z; a3 += xv * w.w;
            }
            red[q][4 * dg + 0] = a0;
            red[q][4 * dg + 1] = a1;
            red[q][4 * dg + 2] = a2;
            red[q][4 * dg + 3] = a3;
            __syncthreads();
            {
                int d = t;
                float s = red[0][d] + red[1][d] + red[2][d] + red[3][d];
                float* dst = g_acc + ((size_t)(g * N_ + p)) * DIM;
                dst[d] += s + ebi[e * DIM + d];   // block-local RMW: safe
            }
        }
        __syncthreads();
    }
}

// ---------------- k_wide0: fan node-pos over all E edge matrices ----------------
__global__ void __launch_bounds__(NTHR) k_wide0(const float* __restrict__ ew,
                                                const float* __restrict__ ebi) {
    __shared__ float sh[G_ * DIM];   // 32 KB
    int st = blockIdx.x;             // 512 blocks: (e, dtile)
    if (st >= E_ * 8) return;
    int e = st >> 3, dt = st & 7;
    int t = threadIdx.x;
    for (int idx = t; idx < G_ * DIM; idx += NTHR) sh[idx] = g_npos[idx];
    __syncthreads();
    int d = dt * 64 + (t & 63);
    int gq = t >> 6;                 // 4 graphs per thread
    const float* W = ew + (size_t)e * DIM * DIM;
    float ac[4] = {0.f, 0.f, 0.f, 0.f};
#pragma unroll 4
    for (int j = 0; j < DIM; j++) {
        float w = W[j * DIM + d];
#pragma unroll
        for (int r = 0; r < 4; r++) ac[r] += sh[(gq * 4 + r) * DIM + j] * w;
    }
    float bv = ebi[e * DIM + d];
#pragma unroll
    for (int r = 0; r < 4; r++) {
        int g = gq * 4 + r;
        int a1i = g_path[g * 8 + 0];
        float val = (g_acc[((size_t)(g * N_ + a1i)) * DIM + d] + ac[r] + bv) * g_dinv[g];
        g_u0[((size_t)(g * E_ + e)) * DIM + d] = fmaxf(val, 0.0f);
    }
}

// ---------------- k_chain: one wide step up the ancestor path -------------------
__global__ void __launch_bounds__(NTHR) k_chain(const float* __restrict__ ew,
                                                const float* __restrict__ ebi,
                                                int k) {
    __shared__ float sh[E_ * 64];    // 16 KB tile of src
    int st = blockIdx.x;             // 128 blocks: (g, dtile)
    if (st >= G_ * 8) return;
    int g = st >> 3, dt = st & 7;
    if (g_plen[g] <= k) return;      // uniform per block
    const float* src = ((k - 1) & 1) ? g_u1 : g_u0;
    float* dst = (k & 1) ? g_u1 : g_u0;
    int am = g_path[g * 8 + (k - 1)];
    int an = g_path[g * 8 + k];
    int em = g_edgesV[am];
    const float* W = ew + (size_t)em * DIM * DIM;
    const float* sp = src + (size_t)g * E_ * DIM;
    float* dp = dst + (size_t)g * E_ * DIM;
    int t = threadIdx.x;
    int d = dt * 64 + (t & 63);
    int eq = t >> 6;                 // 16 e-rows per thread
    float acc[16];
#pragma unroll
    for (int r = 0; r < 16; r++) acc[r] = 0.f;
    for (int j0 = 0; j0 < DIM; j0 += 64) {
        for (int idx = t; idx < E_ * 64; idx += NTHR) {
            int e2 = idx >> 6, jj = idx & 63;
            sh[idx] = sp[e2 * DIM + j0 + jj];
        }
        __syncthreads();
#pragma unroll 2
        for (int jj = 0; jj < 64; jj++) {
            float w = W[(j0 + jj) * DIM + d];
#pragma unroll
            for (int r = 0; r < 16; r++)
                acc[r] += sh[(eq * 16 + r) * 64 + jj] * w;
        }
        __syncthreads();
    }
    float s = g_acc[((size_t)(g * N_ + an)) * DIM + d];
    float bv = ebi[em * DIM + d];
    float dinv = g_dinv[g];
#pragma unroll
    for (int r = 0; r < 16; r++) {
        int e2 = eq * 16 + r;
        dp[e2 * DIM + d] = fmaxf((s + acc[r] + bv) * dinv, 0.0f);
    }
}

// ---------------- k_score ----------------
__global__ void __launch_bounds__(NTHR) k_score(float* __restrict__ out) {
    int wid = blockIdx.x * (NTHR / 32) + (threadIdx.x >> 5);
    int lane = threadIdx.x & 31;
    int NW = gridDim.x * (NTHR / 32);
    for (int task = wid; task < G_ * E_; task += NW) {
        int g = task >> 6, e = task & 63;
        const float* fin = ((g_plen[g] - 1) & 1) ? g_u1 : g_u0;
        const float* row = fin + ((size_t)(g * E_ + e)) * DIM;
        const float* w2 = g_w2 + g * DIM;
        float s = 0.f;
        for (int d = lane; d < DIM; d += 32) s += row[d] * w2[d];
        for (int o = 16; o > 0; o >>= 1) s += __shfl_down_sync(0xffffffffu, s, o);
        if (lane == 0) out[g * E_ + e] = s + g_c0[g];
    }
}

extern "C" void kernel_launch(void* const* d_in, const int* in_sizes, int n_in,
                              void* d_out, int out_size) {
    // ---- size-based dispatch (robust to metadata reordering) ----
    const float *dv = 0, *dw = 0, *db = 0, *ew = 0, *ebi = 0, *sw = 0;
    const void *graphs = 0, *pos = 0;
    const void* i128[3] = { 0, 0, 0 };
    int n128 = 0;
    for (int i = 0; i < n_in; i++) {
        switch (in_sizes[i]) {
            case 102400000: dv  = (const float*)d_in[i]; break;  // [2,100000,512]
            case 524288:    dw  = (const float*)d_in[i]; break;  // [2,512,512]
            case 1024:      db  = (const float*)d_in[i]; break;  // [2,512]
            case 16777216:  ew  = (const float*)d_in[i]; break;  // [64,512,512]
            case 32768:     ebi = (const float*)d_in[i]; break;  // [64,512]
            case 512:       sw  = (const float*)d_in[i]; break;  // [512,1]
            case 2048:      graphs = d_in[i]; break;             // [16,128]
            case 128:       if (n128 < 3) i128[n128++] = d_in[i]; break;
            case 1:         pos = d_in[i]; break;
            default: break;
        }
    }
    // positional fallback (reference signature order)
    if (!dv && n_in > 0)  dv  = (const float*)d_in[0];
    if (!dw && n_in > 1)  dw  = (const float*)d_in[1];
    if (!db && n_in > 2)  db  = (const float*)d_in[2];
    if (!ew && n_in > 3)  ew  = (const float*)d_in[3];
    if (!ebi && n_in > 4) ebi = (const float*)d_in[4];
    if (!sw && n_in > 5)  sw  = (const float*)d_in[5];
    if (n128 < 3) { i128[0] = d_in[6]; i128[1] = d_in[7]; i128[2] = d_in[9]; }
    if (!graphs && n_in > 8) graphs = d_in[8];
    int have_pos = (pos != 0) ? 1 : 0;
    if (!pos) pos = d_in[0];   // unused when have_pos==0

    k_pre<<<1, 128>>>(graphs, i128[0], i128[1], i128[2], pos, have_pos);
    k_base<<<N_, NTHR>>>(dv, dw, db);
    k_w2<<<64, NTHR>>>(ew, ebi, sw);
    k_nar<<<G_, 512>>>(ew, ebi);
    k_wide0<<<E_ * 8, NTHR>>>(ew, ebi);
    for (int k = 1; k <= 4; k++)
        k_chain<<<G_ * 8, NTHR>>>(ew, ebi, k);
    k_score<<<32, NTHR>>>((float*)d_out);
}

// round 17
// speedup vs baseline: 2.0993x; 2.0993x over previous
#include <cuda_runtime.h>
#include <cuda_bf16.h>
#include <cstdint>
#include <cstddef>

typedef long long ll;

#define DIM   512
#define VDIM  512
#define VMAX  100000
#define TMAX  2
#define E_    64
#define N_    128
#define G_    16
#define NTHR  256
#define GB    2                    // graphs per narrow block
#define NPAIR (G_ / GB)            // 8 graph-pairs
#define NARB  (NPAIR * 8)          // 64 narrow blocks (8 slices per pair)

// ---------------- device scratch (static; no allocation) ----------------
__device__ float g_acc[G_ * N_ * DIM];     // per-graph accumulators
__device__ float g_u0[G_ * E_ * DIM];      // wide ping
__device__ float g_u1[G_ * E_ * DIM];      // wide pong
__device__ float g_npos[G_ * DIM];         // finalized embedding of node pos
__device__ float g_w2[G_ * DIM];
__device__ float g_c0[G_];
__device__ float g_dinv[G_];
__device__ int   g_par[G_ * N_];
__device__ int   g_isint[G_ * N_];
__device__ int   g_onp[G_ * N_];
__device__ int   g_path[G_ * 8];
__device__ int   g_plen[G_];
__device__ int   g_eroot[G_];
__device__ int   g_dataV[N_];
__device__ int   g_typesV[N_];
__device__ int   g_edgesV[N_];
__device__ int   g_posv;
__device__ unsigned g_pbc[NPAIR];          // pair-barrier counters
__device__ unsigned g_pbg[NPAIR];          // pair-barrier generations (monotonic)

__device__ __forceinline__ int clampi(int v, int lo, int hi) {
    return v < lo ? lo : (v > hi ? hi : v);
}

// ---------------- k_pre: dtype detection + input canonicalization + topology ----
__global__ void __launch_bounds__(128) k_pre(const void* graphs_raw,
                                             const void* a_raw,
                                             const void* b_raw,
                                             const void* c_raw,
                                             const void* pos_raw,
                                             int have_pos) {
    __shared__ int s_not64;
    __shared__ int s_max[3];
    int t = threadIdx.x;
    if (t == 0) { s_not64 = 0; s_max[0] = s_max[1] = s_max[2] = 0; }
    __syncthreads();

    // dtype detection on graphs buffer (int64 LE shows (val<128, 0) word pairs)
    {
        const unsigned* gw = (const unsigned*)graphs_raw;
        int bad = 0;
        for (int k = t; k < 1024; k += 128) {
            unsigned lo = gw[2 * k], hi = gw[2 * k + 1];
            if (hi != 0u || lo >= 128u) bad = 1;
        }
        if (bad) atomicOr(&s_not64, 1);
    }
    __syncthreads();
    const int is64 = s_not64 ? 0 : 1;

    // value-range classification of the three 128-element int arrays
    const void* abc[3] = { a_raw, b_raw, c_raw };
    for (int arr = 0; arr < 3; arr++) {
        int mx = 0;
        for (int k = t; k < N_; k += 128) {
            int v = is64 ? (int)((const ll*)abc[arr])[k] : ((const int*)abc[arr])[k];
            if (v > mx) mx = v;
        }
        atomicMax(&s_max[arr], mx);
    }
    __syncthreads();

    int di = 0, ti = 0, ei;
    {
        int mx0 = s_max[0], mx1 = s_max[1], mx2 = s_max[2];
        di = (mx1 > mx0) ? 1 : 0;
        if (mx2 > ((di == 0) ? mx0 : mx1)) di = 2;
        ti = (mx1 < mx0) ? 1 : 0;
        if (mx2 < ((ti == 0) ? mx0 : mx1)) ti = 2;
        if (ti == di) { di = 0; ti = 1; }
        ei = 3 - di - ti;
    }

    for (int k = t; k < N_; k += 128) {
        int dvv = is64 ? (int)((const ll*)abc[di])[k] : ((const int*)abc[di])[k];
        int tvv = is64 ? (int)((const ll*)abc[ti])[k] : ((const int*)abc[ti])[k];
        int evv = is64 ? (int)((const ll*)abc[ei])[k] : ((const int*)abc[ei])[k];
        g_dataV[k]  = clampi(dvv, 0, VMAX - 1);
        g_typesV[k] = clampi(tvv, 0, TMAX - 1);
        g_edgesV[k] = clampi(evv, 0, E_ - 1);
    }
    for (int k = t; k < G_ * N_; k += 128) g_onp[k] = 0;
    for (int k = t; k < G_ * 8; k += 128) g_path[k] = 0;
    for (int k = t; k < NPAIR; k += 128) g_pbc[k] = 0;
    if (t == 0) {
        int pv = have_pos ? ((const int*)pos_raw)[0] : 5;
        g_posv = clampi(pv, 0, N_ - 1);
    }
    __syncthreads();

    const int posv = g_posv;
    if (t < G_) {
        int g = t;
        int par[N_], cnt[N_];
        for (int i = 0; i < N_; i++) {
            int p = is64 ? (int)((const ll*)graphs_raw)[(size_t)g * N_ + i]
                         : ((const int*)graphs_raw)[(size_t)g * N_ + i];
            par[i] = clampi(p, 0, N_ - 1);
        }
        int prev = -1, root = 0;
        for (int i = 0; i < N_; i++) {
            if (par[i] == i) { if (prev >= 0) par[prev] = i; prev = i; root = i; }
        }
        par[root] = -1;
        for (int i = 0; i < N_; i++) cnt[i] = 0;
        for (int c = 0; c < N_; c++) if (par[c] >= 0) cnt[par[c]]++;
        int nint = 0;
        for (int i = 0; i < N_; i++) if (cnt[i] > 0) nint++;
        g_dinv[g] = 1.0f / (float)(nint + 1);
        int L = 0, a = par[posv];
        while (a >= 0 && L < 8) {
            g_path[g * 8 + L] = a;
            g_onp[g * N_ + a] = 1;
            L++;
            a = par[a];
        }
        g_plen[g] = L;
        g_eroot[g] = g_edgesV[root];
        for (int i = 0; i < N_; i++) {
            g_par[g * N_ + i] = par[i];
            g_isint[g * N_ + i] = (cnt[i] > 0) ? 1 : 0;
        }
    }
}

// ---------------- k_base: base embeddings, replicated per graph ----------------
__global__ void __launch_bounds__(NTHR) k_base(const float* __restrict__ dv,
                                               const float* __restrict__ dw,
                                               const float* __restrict__ db) {
    __shared__ float sh[VDIM];
    int node = blockIdx.x;
    if (node >= N_) return;
    int t = threadIdx.x;
    int ty = g_typesV[node];
    int dr = g_dataV[node];
    const float* sel = dv + ((size_t)ty * VMAX + (size_t)dr) * VDIM;
    for (int j = t; j < VDIM; j += NTHR) sh[j] = sel[j];
    __syncthreads();
    const float* W = dw + (size_t)ty * VDIM * DIM;
    int d0 = t, d1 = t + NTHR;
    float a0 = 0.f, a1 = 0.f;
#pragma unroll 4
    for (int j = 0; j < VDIM; j++) {
        float v = sh[j];
        a0 += v * W[j * DIM + d0];
        a1 += v * W[j * DIM + d1];
    }
    a0 += db[ty * DIM + d0];
    a1 += db[ty * DIM + d1];
    for (int g = 0; g < G_; g++) {
        g_acc[((size_t)(g * N_ + node)) * DIM + d0] = a0;
        g_acc[((size_t)(g * N_ + node)) * DIM + d1] = a1;
    }
}

// ---------------- k_w2: fold root edge matrix + score weights ----------------
__global__ void __launch_bounds__(NTHR) k_w2(const float* __restrict__ ew,
                                             const float* __restrict__ ebi,
                                             const float* __restrict__ sw) {
    int wid = blockIdx.x * (NTHR / 32) + (threadIdx.x >> 5);
    int lane = threadIdx.x & 31;
    int NW = gridDim.x * (NTHR / 32);
    for (int task = wid; task < G_ * DIM + G_; task += NW) {
        if (task < G_ * DIM) {
            int g = task / DIM, j = task % DIM;
            const float* Wr = ew + ((size_t)g_eroot[g] * DIM + j) * DIM;
            float s = 0.f;
            for (int d = lane; d < DIM; d += 32) s += Wr[d] * sw[d];
            for (int o = 16; o > 0; o >>= 1) s += __shfl_down_sync(0xffffffffu, s, o);
            if (lane == 0) g_w2[g * DIM + j] = s;
        } else {
            int g = task - G_ * DIM;
            const float* br = ebi + (size_t)g_eroot[g] * DIM;
            float s = 0.f;
            for (int d = lane; d < DIM; d += 32) s += br[d] * sw[d];
            for (int o = 16; o > 0; o >>= 1) s += __shfl_down_sync(0xffffffffu, s, o);
            if (lane == 0) g_c0[g] = s;
        }
    }
}

// ---------------- k_nar2: slice-parallel, 2-graph-batched narrow phase ----------
// 64 blocks: pair = b>>3 (graphs 2*pair, 2*pair+1), slice s = b&7 (cols [64s,64s+64)).
// Descending node order is topological (parent<child). Accumulator slices are
// owner-exclusive (plain RMW). Only internal-node finalize needs the 8-block
// pair barrier (leaves' x is the untouched base; pos is slice-local).
__global__ void __launch_bounds__(512) k_nar2(const float* __restrict__ ew,
                                              const float* __restrict__ ebi) {
    __shared__ float x[GB][DIM];               // 4 KB
    __shared__ float red[GB][16][64];          // 8 KB
    __shared__ int   spar[GB][N_];
    __shared__ int   scode[GB][N_];            // 0 skip,1 leaf,2 internal,3 pos-leaf,4 pos-int
    __shared__ int   sedge[N_];

    const int t = threadIdx.x;
    const int pair = blockIdx.x >> 3;
    const int s = blockIdx.x & 7;
    const int g0 = pair * GB;
    const int posv = g_posv;
    const float dinv0 = g_dinv[g0];
    const float dinv1 = g_dinv[g0 + 1];

    for (int k = t; k < N_; k += 512) sedge[k] = g_edgesV[k];
    for (int k = t; k < GB * N_; k += 512) {
        int gg = k / N_, i = k % N_;
        int g = g0 + gg;
        int p = g_par[g * N_ + i];
        spar[gg][i] = p;
        int code;
        if (p < 0 || g_onp[g * N_ + i]) code = 0;
        else if (i == posv) code = g_isint[g * N_ + i] ? 4 : 3;
        else code = g_isint[g * N_ + i] ? 2 : 1;
        scode[gg][i] = code;
    }
    __syncthreads();

    const int jsl = t >> 4;        // 0..31 (16 j each)
    const int dg  = t & 15;        // 0..15 (float4 col groups)

    for (int i = N_ - 1; i >= 1; i--) {
        int c0 = scode[0][i], c1 = scode[1][i];
        if (c0 == 0 && c1 == 0) continue;

        // stage 1: finalize owned slice (store-back / npos)
        if (t < 64) {
            int col = s * 64 + t;
#pragma unroll
            for (int gg = 0; gg < GB; gg++) {
                int code = (gg == 0) ? c0 : c1;
                if (code < 2) continue;                  // skip / leaf: untouched
                int g = g0 + gg;
                float dinv = (gg == 0) ? dinv0 : dinv1;
                float* ap = g_acc + ((size_t)(g * N_ + i)) * DIM + col;
                float v = *ap;
                if (code != 3) v = fmaxf(v * dinv, 0.0f);   // internal (2 or 4)
                if (code >= 3) g_npos[g * DIM + col] = v;    // pos
                else *ap = v;                                // store-back (code 2)
            }
        }
        bool need_bar = (c0 == 2) || (c1 == 2);
        if (need_bar) {
            __threadfence();
            __syncthreads();
            if (t == 0) {
                unsigned gen = *((volatile unsigned*)&g_pbg[pair]);
                unsigned old = atomicAdd(&g_pbc[pair], 1u);
                if (old == 7u) {
                    g_pbc[pair] = 0;
                    __threadfence();
                    atomicAdd(&g_pbg[pair], 1u);
                } else {
                    while (*((volatile unsigned*)&g_pbg[pair]) == gen) { __nanosleep(32); }
                }
                __threadfence();
            }
            __syncthreads();
        }

        bool mv0 = (c0 == 1 || c0 == 2);
        bool mv1 = (c1 == 1 || c1 == 2);
        if (!mv0 && !mv1) { __syncthreads(); continue; }

        // stage 2: broadcast full x into smem
        x[0][t] = mv0 ? __ldcg(g_acc + ((size_t)(g0 * N_ + i)) * DIM + t) : 0.0f;
        x[1][t] = mv1 ? __ldcg(g_acc + ((size_t)((g0 + 1) * N_ + i)) * DIM + t) : 0.0f;
        __syncthreads();

        // stage 3: batched matvec — W float4 loaded once, used for both graphs
        int e = sedge[i];
        const float4* W4 = (const float4*)(ew + (size_t)e * DIM * DIM) + (s * 16 + dg);
        float4 A0 = {0.f, 0.f, 0.f, 0.f};
        float4 A1 = {0.f, 0.f, 0.f, 0.f};
#pragma unroll 8
        for (int jj = 0; jj < 16; jj++) {
            int j = jsl * 16 + jj;
            float4 w = W4[(size_t)j * (DIM / 4)];
            float v0 = x[0][j];
            A0.x += v0 * w.x; A0.y += v0 * w.y; A0.z += v0 * w.z; A0.w += v0 * w.w;
            float v1 = x[1][j];
            A1.x += v1 * w.x; A1.y += v1 * w.y; A1.z += v1 * w.z; A1.w += v1 * w.w;
        }
        // warp pre-reduce: combine jsl pairs (lanes 16 apart share dg)
        A0.x += __shfl_down_sync(0xffffffffu, A0.x, 16);
        A0.y += __shfl_down_sync(0xffffffffu, A0.y, 16);
        A0.z += __shfl_down_sync(0xffffffffu, A0.z, 16);
        A0.w += __shfl_down_sync(0xffffffffu, A0.w, 16);
        A1.x += __shfl_down_sync(0xffffffffu, A1.x, 16);
        A1.y += __shfl_down_sync(0xffffffffu, A1.y, 16);
        A1.z += __shfl_down_sync(0xffffffffu, A1.z, 16);
        A1.w += __shfl_down_sync(0xffffffffu, A1.w, 16);
        if ((t & 16) == 0) {
            int w = t >> 5;                    // 0..15
            red[0][w][dg * 4 + 0] = A0.x;
            red[0][w][dg * 4 + 1] = A0.y;
            red[0][w][dg * 4 + 2] = A0.z;
            red[0][w][dg * 4 + 3] = A0.w;
            red[1][w][dg * 4 + 0] = A1.x;
            red[1][w][dg * 4 + 1] = A1.y;
            red[1][w][dg * 4 + 2] = A1.z;
            red[1][w][dg * 4 + 3] = A1.w;
        }
        __syncthreads();
        if (t < 128) {
            int gg = t >> 6, c = t & 63;
            bool mv = (gg == 0) ? mv0 : mv1;
            if (mv) {
                float sum = 0.f;
#pragma unroll
                for (int w = 0; w < 16; w++) sum += red[gg][w][c];
                int col = s * 64 + c;
                int g = g0 + gg;
                int p = spar[gg][i];
                float* dst = g_acc + ((size_t)(g * N_ + p)) * DIM + col;
                *dst += sum + ebi[e * DIM + col];    // owner-exclusive RMW
            }
        }
        __syncthreads();
    }
}

// ---------------- k_wide0: fan node-pos over all E edge matrices ----------------
__global__ void __launch_bounds__(NTHR) k_wide0(const float* __restrict__ ew,
                                                const float* __restrict__ ebi) {
    __shared__ float sh[G_ * DIM];   // 32 KB
    int st = blockIdx.x;             // 512 blocks: (e, dtile)
    if (st >= E_ * 8) return;
    int e = st >> 3, dt = st & 7;
    int t = threadIdx.x;
    for (int idx = t; idx < G_ * DIM; idx += NTHR) sh[idx] = g_npos[idx];
    __syncthreads();
    int d = dt * 64 + (t & 63);
    int gq = t >> 6;                 // 4 graphs per thread
    const float* W = ew + (size_t)e * DIM * DIM;
    float ac[4] = {0.f, 0.f, 0.f, 0.f};
#pragma unroll 4
    for (int j = 0; j < DIM; j++) {
        float w = W[j * DIM + d];
#pragma unroll
        for (int r = 0; r < 4; r++) ac[r] += sh[(gq * 4 + r) * DIM + j] * w;
    }
    float bv = ebi[e * DIM + d];
#pragma unroll
    for (int r = 0; r < 4; r++) {
        int g = gq * 4 + r;
        int a1i = g_path[g * 8 + 0];
        float val = (g_acc[((size_t)(g * N_ + a1i)) * DIM + d] + ac[r] + bv) * g_dinv[g];
        g_u0[((size_t)(g * E_ + e)) * DIM + d] = fmaxf(val, 0.0f);
    }
}

// ---------------- k_chain: one wide step up the ancestor path -------------------
__global__ void __launch_bounds__(NTHR) k_chain(const float* __restrict__ ew,
                                                const float* __restrict__ ebi,
                                                int k) {
    __shared__ float sh[E_ * 64];    // 16 KB tile of src
    int st = blockIdx.x;             // 128 blocks: (g, dtile)
    if (st >= G_ * 8) return;
    int g = st >> 3, dt = st & 7;
    if (g_plen[g] <= k) return;      // uniform per block
    const float* src = ((k - 1) & 1) ? g_u1 : g_u0;
    float* dst = (k & 1) ? g_u1 : g_u0;
    int am = g_path[g * 8 + (k - 1)];
    int an = g_path[g * 8 + k];
    int em = g_edgesV[am];
    const float* W = ew + (size_t)em * DIM * DIM;
    const float* sp = src + (size_t)g * E_ * DIM;
    float* dp = dst + (size_t)g * E_ * DIM;
    int t = threadIdx.x;
    int d = dt * 64 + (t & 63);
    int eq = t >> 6;                 // 16 e-rows per thread
    float acc[16];
#pragma unroll
    for (int r = 0; r < 16; r++) acc[r] = 0.f;
    for (int j0 = 0; j0 < DIM; j0 += 64) {
        for (int idx = t; idx < E_ * 64; idx += NTHR) {
            int e2 = idx >> 6, jj = idx & 63;
            sh[idx] = sp[e2 * DIM + j0 + jj];
        }
        __syncthreads();
#pragma unroll 2
        for (int jj = 0; jj < 64; jj++) {
            float w = W[(j0 + jj) * DIM + d];
#pragma unroll
            for (int r = 0; r < 16; r++)
                acc[r] += sh[(eq * 16 + r) * 64 + jj] * w;
        }
        __syncthreads();
    }
    float s = g_acc[((size_t)(g * N_ + an)) * DIM + d];
    float bv = ebi[em * DIM + d];
    float dinv = g_dinv[g];
#pragma unroll
    for (int r = 0; r < 16; r++) {
        int e2 = eq * 16 + r;
        dp[e2 * DIM + d] = fmaxf((s + acc[r] + bv) * dinv, 0.0f);
    }
}

// ---------------- k_score ----------------
__global__ void __launch_bounds__(NTHR) k_score(float* __restrict__ out) {
    int wid = blockIdx.x * (NTHR / 32) + (threadIdx.x >> 5);
    int lane = threadIdx.x & 31;
    int NW = gridDim.x * (NTHR / 32);
    for (int task = wid; task < G_ * E_; task += NW) {
        int g = task >> 6, e = task & 63;
        const float* fin = ((g_plen[g] - 1) & 1) ? g_u1 : g_u0;
        const float* row = fin + ((size_t)(g * E_ + e)) * DIM;
        const float* w2 = g_w2 + g * DIM;
        float s = 0.f;
        for (int d = lane; d < DIM; d += 32) s += row[d] * w2[d];
        for (int o = 16; o > 0; o >>= 1) s += __shfl_down_sync(0xffffffffu, s, o);
        if (lane == 0) out[g * E_ + e] = s + g_c0[g];
    }
}

extern "C" void kernel_launch(void* const* d_in, const int* in_sizes, int n_in,
                              void* d_out, int out_size) {
    const float *dv = 0, *dw = 0, *db = 0, *ew = 0, *ebi = 0, *sw = 0;
    const void *graphs = 0, *pos = 0;
    const void* i128[3] = { 0, 0, 0 };
    int n128 = 0;
    for (int i = 0; i < n_in; i++) {
        switch (in_sizes[i]) {
            case 102400000: dv  = (const float*)d_in[i]; break;
            case 524288:    dw  = (const float*)d_in[i]; break;
            case 1024:      db  = (const float*)d_in[i]; break;
            case 16777216:  ew  = (const float*)d_in[i]; break;
            case 32768:     ebi = (const float*)d_in[i]; break;
            case 512:       sw  = (const float*)d_in[i]; break;
            case 2048:      graphs = d_in[i]; break;
            case 128:       if (n128 < 3) i128[n128++] = d_in[i]; break;
            case 1:         pos = d_in[i]; break;
            default: break;
        }
    }
    if (!dv && n_in > 0)  dv  = (const float*)d_in[0];
    if (!dw && n_in > 1)  dw  = (const float*)d_in[1];
    if (!db && n_in > 2)  db  = (const float*)d_in[2];
    if (!ew && n_in > 3)  ew  = (const float*)d_in[3];
    if (!ebi && n_in > 4) ebi = (const float*)d_in[4];
    if (!sw && n_in > 5)  sw  = (const float*)d_in[5];
    if (n128 < 3) { i128[0] = d_in[6]; i128[1] = d_in[7]; i128[2] = d_in[9]; }
    if (!graphs && n_in > 8) graphs = d_in[8];
    int have_pos = (pos != 0) ? 1 : 0;
    if (!pos) pos = d_in[0];

    k_pre<<<1, 128>>>(graphs, i128[0], i128[1], i128[2], pos, have_pos);
    k_base<<<N_, NTHR>>>(dv, dw, db);
    k_w2<<<64, NTHR>>>(ew, ebi, sw);
    k_nar2<<<NARB, 512>>>(ew, ebi);
    k_wide0<<<E_ * 8, NTHR>>>(ew, ebi);
    for (int k = 1; k <= 4; k++)
        k_chain<<<G_ * 8, NTHR>>>(ew, ebi, k);
    k_score<<<32, NTHR>>>((float*)d_out);
}